// round 16
// baseline (speedup 1.0000x reference)
#include <cuda_runtime.h>
#include <cuda_bf16.h>
#include <math.h>
#include <float.h>

// Problem constants
#define BB    4
#define STF   8      // teacher frames
#define SSF   4      // student frames
#define PP    1024
#define DD    1024
#define NREF  256
#define NTOP  4
#define ME    4096   // extra rows per batch (4 frames * 1024)
#define MT    32     // m-tiles (ME/128)
#define NKL   (NREF * BB)   // k_kl blocks = 1024

// Scratch (device globals; no allocation allowed)
__device__ __nv_bfloat16  g_rthb[BB][NREF][DD];  // normalized teacher ref rows (bf16)
__device__ float          g_pv  [BB][NREF][MT][4]; // per-mtile top4 values
__device__ int            g_pi  [BB][NREF][MT][4]; // per-mtile top4 indices
__device__ int            g_top [BB][NREF][NTOP];
__device__ double         g_acc [3];
__device__ unsigned       g_done;

// ---------------------------------------------------------------- helpers

__device__ __forceinline__ float warpSum(float v){
    #pragma unroll
    for (int o = 16; o > 0; o >>= 1) v += __shfl_xor_sync(0xffffffffu, v, o);
    return v;
}

__device__ __forceinline__ float blockSum256(float v, volatile float* sm){
    __syncthreads();
    int lane = threadIdx.x & 31, w = threadIdx.x >> 5;
    v = warpSum(v);
    if (lane == 0) sm[w] = v;
    __syncthreads();
    if (threadIdx.x == 0){
        float r = sm[0];
        #pragma unroll
        for (int i = 1; i < 8; i++) r += sm[i];
        sm[0] = r;
    }
    __syncthreads();
    return sm[0];
}

// insert candidate (v,i) into top-4 sorted desc (ties -> lower index first)
__device__ __forceinline__ void ins4(float v, int i, float* tv, int* ti){
    if (v > tv[3] || (v == tv[3] && i < ti[3])){
        tv[3] = v; ti[3] = i;
        #pragma unroll
        for (int k = 3; k > 0; k--){
            bool sw = (tv[k] > tv[k-1]) || (tv[k] == tv[k-1] && ti[k] < ti[k-1]);
            if (sw){
                float fv = tv[k]; tv[k] = tv[k-1]; tv[k-1] = fv;
                int   fi = ti[k]; ti[k] = ti[k-1]; ti[k-1] = fi;
            } else break;
        }
    }
}

__device__ __forceinline__ float huber(float kl){
    float ax = fabsf(kl);
    return (ax < 0.5f) ? (ax * ax) : (ax - 0.25f);
}

// ---------------------------------------------------------------- mma helpers

__device__ __forceinline__ void ldsm4(unsigned& r0, unsigned& r1, unsigned& r2, unsigned& r3,
                                      unsigned addr){
    asm volatile("ldmatrix.sync.aligned.m8n8.x4.shared.b16 {%0,%1,%2,%3}, [%4];"
                 : "=r"(r0), "=r"(r1), "=r"(r2), "=r"(r3) : "r"(addr));
}
__device__ __forceinline__ void mma16816(float* c, const unsigned* a, const unsigned* b){
    asm volatile("mma.sync.aligned.m16n8k16.row.col.f32.bf16.bf16.f32 "
                 "{%0,%1,%2,%3}, {%4,%5,%6,%7}, {%8,%9}, {%0,%1,%2,%3};"
                 : "+f"(c[0]), "+f"(c[1]), "+f"(c[2]), "+f"(c[3])
                 : "r"(a[0]), "r"(a[1]), "r"(a[2]), "r"(a[3]), "r"(b[0]), "r"(b[1]));
}
__device__ __forceinline__ unsigned f2bf2(float lo, float hi){
    __nv_bfloat162 h = __floats2bfloat162_rn(lo, hi);
    return *(unsigned*)&h;
}

// ---------------------------------------------------------------- kernels

// Normalize teacher ref rows (frame 0) to bf16. grid(NREF, BB), 256 thr.
// Also zeroes the loss accumulators / ticket (block 0,0).
__global__ void k_gather_ref(const float* __restrict__ T, const int* __restrict__ rp){
    __shared__ float sm[8];
    int n = blockIdx.x, b = blockIdx.y, tid = threadIdx.x;
    if (n == 0 && b == 0 && tid == 0){
        g_acc[0] = 0.0; g_acc[1] = 0.0; g_acc[2] = 0.0;
        g_done = 0u;
    }
    int p = rp[n];
    const float* tr = T + (((size_t)b * STF + 0) * PP + p) * DD;
    float xv[4], ss = 0.f;
    #pragma unroll
    for (int j = 0; j < 4; j++){
        int idx = tid + j * 256;
        xv[j] = tr[idx];
        ss += xv[j] * xv[j];
    }
    ss = blockSum256(ss, sm);
    float inv = 1.f / fmaxf(sqrtf(ss), 1e-12f);
    #pragma unroll
    for (int j = 0; j < 4; j++){
        int idx = tid + j * 256;
        g_rthb[b][n][idx] = __float2bfloat16(xv[j] * inv);
    }
}

// bf16 tensor-core GEMM + fused extra-row norms + fused per-block top-4.
// Block tile 128(ref) x 128(extra) x 32(k). 8 warps: 2(ref) x 4(extra).
// Double-buffered smem stages: ONE barrier per k-iter (R4-vs-R6 evidence:
// this mainloop was ~7us faster head-to-head than the single-buffer one).
#define LDSS 40   // smem row stride in bf16 elems
#define STAGE_B 20480
__global__ void __launch_bounds__(256, 2) k_gemm(const float* __restrict__ T){
    __shared__ __align__(16) unsigned char sbuf[2 * STAGE_B];
    __shared__ float sm_inv[128];
    float (*cv)[4][4] = reinterpret_cast<float(*)[4][4]>(sbuf);        // 8 KB (stage 0)
    int   (*ci)[4][4] = reinterpret_cast<int  (*)[4][4]>(sbuf + 8192); // 8 KB

    int mt = blockIdx.x, nt = blockIdx.y, b = blockIdx.z;
    int tid = threadIdx.x, lane = tid & 31, warp = tid >> 5;
    int wn = warp & 1;    // ref-dim warp (64 rows)
    int wm = warp >> 1;   // extra-dim warp (32 rows)

    const __nv_bfloat16* A = &g_rthb[b][nt * 128][0];
    int m0 = mt * 128;
    int frame = 2 * (m0 >> 10) + 1;
    const float* Bp = T + (((size_t)b * STF + frame) * PP + (m0 & 1023)) * DD;

    float acc[4][4][4];
    #pragma unroll
    for (int i = 0; i < 4; i++)
        #pragma unroll
        for (int j = 0; j < 4; j++)
            #pragma unroll
            for (int q = 0; q < 4; q++) acc[i][j][q] = 0.f;

    unsigned sbase = (unsigned)__cvta_generic_to_shared(sbuf);

    int row_a = tid >> 1;
    int csel  = (tid & 1) * 16;
    float ssq = 0.f;

    uint4  ar0, ar1;
    float4 br0, br1, br2, br3;

    // prefetch + store stage 0
    {
        const uint4*  ap = (const uint4*)(A + (size_t)row_a * DD + csel);
        const float4* bp = (const float4*)(Bp + (size_t)row_a * DD + csel);
        ar0 = ap[0]; ar1 = ap[1];
        br0 = bp[0]; br1 = bp[1]; br2 = bp[2]; br3 = bp[3];
        __nv_bfloat16* As0 = reinterpret_cast<__nv_bfloat16*>(sbuf);
        __nv_bfloat16* Bs0 = reinterpret_cast<__nv_bfloat16*>(sbuf + 10240);
        *(uint4*)&As0[row_a * LDSS + csel]     = ar0;
        *(uint4*)&As0[row_a * LDSS + csel + 8] = ar1;
        ssq += br0.x*br0.x + br0.y*br0.y + br0.z*br0.z + br0.w*br0.w
             + br1.x*br1.x + br1.y*br1.y + br1.z*br1.z + br1.w*br1.w
             + br2.x*br2.x + br2.y*br2.y + br2.z*br2.z + br2.w*br2.w
             + br3.x*br3.x + br3.y*br3.y + br3.z*br3.z + br3.w*br3.w;
        uint4 bb0, bb1;
        bb0.x = f2bf2(br0.x, br0.y); bb0.y = f2bf2(br0.z, br0.w);
        bb0.z = f2bf2(br1.x, br1.y); bb0.w = f2bf2(br1.z, br1.w);
        bb1.x = f2bf2(br2.x, br2.y); bb1.y = f2bf2(br2.z, br2.w);
        bb1.z = f2bf2(br3.x, br3.y); bb1.w = f2bf2(br3.z, br3.w);
        *(uint4*)&Bs0[row_a * LDSS + csel]     = bb0;
        *(uint4*)&Bs0[row_a * LDSS + csel + 8] = bb1;
    }
    __syncthreads();

    for (int kt = 0; kt < DD / 32; kt++){
        unsigned cur = (unsigned)(kt & 1) * STAGE_B;
        unsigned nxt = cur ^ STAGE_B;
        bool more = (kt < DD / 32 - 1);

        // issue global prefetch for tile kt+1 (long latency, overlapped with mma)
        if (more){
            int k0 = (kt + 1) * 32;
            const uint4*  ap = (const uint4*)(A + (size_t)row_a * DD + k0 + csel);
            const float4* bp = (const float4*)(Bp + (size_t)row_a * DD + k0 + csel);
            ar0 = ap[0]; ar1 = ap[1];
            br0 = bp[0]; br1 = bp[1]; br2 = bp[2]; br3 = bp[3];
        }

        unsigned sA = sbase + cur;
        unsigned sB = sbase + cur + 10240;
        #pragma unroll
        for (int kk = 0; kk < 32; kk += 16){
            unsigned af[4][4];
            #pragma unroll
            for (int mi = 0; mi < 4; mi++){
                int r = wn * 64 + mi * 16 + (lane & 15);
                int c = kk + ((lane >> 4) << 3);
                ldsm4(af[mi][0], af[mi][1], af[mi][2], af[mi][3],
                      sA + (unsigned)((r * LDSS + c) * 2));
            }
            unsigned bf[4][2];
            #pragma unroll
            for (int pr = 0; pr < 2; pr++){
                int r = wm * 32 + pr * 16 + (lane & 7) + ((lane >> 4) << 3);
                int c = kk + (((lane >> 3) & 1) << 3);
                unsigned t0, t1, t2, t3;
                ldsm4(t0, t1, t2, t3, sB + (unsigned)((r * LDSS + c) * 2));
                bf[pr*2  ][0] = t0; bf[pr*2  ][1] = t1;
                bf[pr*2+1][0] = t2; bf[pr*2+1][1] = t3;
            }
            #pragma unroll
            for (int mi = 0; mi < 4; mi++)
                #pragma unroll
                for (int ni = 0; ni < 4; ni++)
                    mma16816(acc[mi][ni], af[mi], bf[ni]);
        }

        // convert + store tile kt+1 into the other stage
        if (more){
            __nv_bfloat16* Asn = reinterpret_cast<__nv_bfloat16*>(sbuf + nxt);
            __nv_bfloat16* Bsn = reinterpret_cast<__nv_bfloat16*>(sbuf + nxt + 10240);
            *(uint4*)&Asn[row_a * LDSS + csel]     = ar0;
            *(uint4*)&Asn[row_a * LDSS + csel + 8] = ar1;
            ssq += br0.x*br0.x + br0.y*br0.y + br0.z*br0.z + br0.w*br0.w
                 + br1.x*br1.x + br1.y*br1.y + br1.z*br1.z + br1.w*br1.w
                 + br2.x*br2.x + br2.y*br2.y + br2.z*br2.z + br2.w*br2.w
                 + br3.x*br3.x + br3.y*br3.y + br3.z*br3.z + br3.w*br3.w;
            uint4 bb0, bb1;
            bb0.x = f2bf2(br0.x, br0.y); bb0.y = f2bf2(br0.z, br0.w);
            bb0.z = f2bf2(br1.x, br1.y); bb0.w = f2bf2(br1.z, br1.w);
            bb1.x = f2bf2(br2.x, br2.y); bb1.y = f2bf2(br2.z, br2.w);
            bb1.z = f2bf2(br3.x, br3.y); bb1.w = f2bf2(br3.z, br3.w);
            *(uint4*)&Bsn[row_a * LDSS + csel]     = bb0;
            *(uint4*)&Bsn[row_a * LDSS + csel + 8] = bb1;
        }
        __syncthreads();
    }

    // ---- fused inverse norms (per local extra row) ----
    ssq += __shfl_xor_sync(0xffffffffu, ssq, 1);
    if ((tid & 1) == 0)
        sm_inv[row_a] = 1.f / fmaxf(sqrtf(ssq), 1e-12f);
    __syncthreads();

    // ---- fused per-block top-4 per ref row ----
    int gm = lane >> 2, gn = (lane & 3) * 2;
    #pragma unroll
    for (int mi = 0; mi < 4; mi++){
        #pragma unroll
        for (int h = 0; h < 2; h++){
            int r = wn * 64 + mi * 16 + gm + h * 8;   // local ref row
            float tv[4] = {-FLT_MAX, -FLT_MAX, -FLT_MAX, -FLT_MAX};
            int   ti[4] = {0x7fffffff, 0x7fffffff, 0x7fffffff, 0x7fffffff};
            #pragma unroll
            for (int ni = 0; ni < 4; ni++){
                int c = wm * 32 + ni * 8 + gn;
                ins4(acc[mi][ni][h*2+0] * sm_inv[c],     m0 + c,     tv, ti);
                ins4(acc[mi][ni][h*2+1] * sm_inv[c + 1], m0 + c + 1, tv, ti);
            }
            #pragma unroll
            for (int st = 1; st <= 2; st <<= 1){
                float ov[4]; int oi[4];
                #pragma unroll
                for (int k = 0; k < 4; k++){
                    ov[k] = __shfl_xor_sync(0xffffffffu, tv[k], st);
                    oi[k] = __shfl_xor_sync(0xffffffffu, ti[k], st);
                }
                #pragma unroll
                for (int k = 0; k < 4; k++) ins4(ov[k], oi[k], tv, ti);
            }
            if ((lane & 3) == 0){
                #pragma unroll
                for (int k = 0; k < 4; k++){ cv[r][wm][k] = tv[k]; ci[r][wm][k] = ti[k]; }
            }
        }
    }
    __syncthreads();

    if (tid < 128){
        float tv[4] = {-FLT_MAX, -FLT_MAX, -FLT_MAX, -FLT_MAX};
        int   ti[4] = {0x7fffffff, 0x7fffffff, 0x7fffffff, 0x7fffffff};
        #pragma unroll
        for (int w = 0; w < 4; w++)
            #pragma unroll
            for (int k = 0; k < 4; k++) ins4(cv[tid][w][k], ci[tid][w][k], tv, ti);
        int n = nt * 128 + tid;
        *(float4*)&g_pv[b][n][mt][0] = make_float4(tv[0], tv[1], tv[2], tv[3]);
        *(int4*)  &g_pi[b][n][mt][0] = make_int4(ti[0], ti[1], ti[2], ti[3]);
    }
}

// Warp-parallel final top-4 reduce over 32 m-tile candidate sets.
// 8 warps/block, warp w handles (b, n = blockIdx.x*8 + w). grid(NREF/8, BB).
__global__ void k_topk2(){
    int w = threadIdx.x >> 5, lane = threadIdx.x & 31;
    int n = blockIdx.x * 8 + w, b = blockIdx.y;
    float4 pv = *(const float4*)&g_pv[b][n][lane][0];
    int4   pi = *(const int4*)  &g_pi[b][n][lane][0];
    float tv[4] = {-FLT_MAX, -FLT_MAX, -FLT_MAX, -FLT_MAX};
    int   ti[4] = {0x7fffffff, 0x7fffffff, 0x7fffffff, 0x7fffffff};
    ins4(pv.x, pi.x, tv, ti); ins4(pv.y, pi.y, tv, ti);
    ins4(pv.z, pi.z, tv, ti); ins4(pv.w, pi.w, tv, ti);
    #pragma unroll
    for (int st = 1; st <= 16; st <<= 1){
        float ov[4]; int oi[4];
        #pragma unroll
        for (int k = 0; k < 4; k++){
            ov[k] = __shfl_xor_sync(0xffffffffu, tv[k], st);
            oi[k] = __shfl_xor_sync(0xffffffffu, ti[k], st);
        }
        #pragma unroll
        for (int k = 0; k < 4; k++) ins4(ov[k], oi[k], tv, ti);
    }
    if (lane == 0){
        #pragma unroll
        for (int k = 0; k < 4; k++) g_top[b][n][k] = ti[k];
    }
}

// All 19 KL tasks for one (b,n): one task per warp, 19 warps (608 threads).
// grid(NREF, BB). Ref rows read directly from T/S at rp[n].
//   w 0-2 : d1 (tt = w)
//   w 3-6 : d2 (j = w-3), t-invariant -> weighted x3
//   w 7-18: d3 (tt = (w-7)/4, j = (w-7)%4)
// Single streaming pass, no max-shift. Last block writes the final loss.
__global__ void __launch_bounds__(608) k_kl(const float* __restrict__ T,
                                            const float* __restrict__ S,
                                            const int* __restrict__ sp,
                                            const int* __restrict__ rp,
                                            float* __restrict__ out){
    __shared__ float res[19];
    int n = blockIdx.x, b = blockIdx.y;
    int w = threadIdx.x >> 5, lane = threadIdx.x & 31;

    const int T_IDX[3] = {2, 4, 6};
    const int S_IDX[3] = {1, 2, 3};
    int p  = sp[n];
    int pr = rp[n];
    const float* rt = T + (((size_t)b * STF + 0) * PP + pr) * DD;
    const float* rs = S + (((size_t)b * SSF + 0) * PP + pr) * DD;

    const float *xa, *xb, *ya, *yb;
    if (w < 3){
        int tt = w;
        xa = rt;
        xb = T + (((size_t)b * STF + T_IDX[tt]) * PP + p) * DD;
        ya = rs;
        yb = S + (((size_t)b * SSF + S_IDX[tt]) * PP + p) * DD;
    } else {
        int j = (w < 7) ? (w - 3) : ((w - 7) & 3);
        int m = g_top[b][n][j];
        int frame = 2 * (m >> 10) + 1;
        const float* sh = T + (((size_t)b * STF + frame) * PP + (m & 1023)) * DD;
        if (w < 7){
            xa = rt; ya = rs;
        } else {
            int tt = (w - 7) >> 2;
            xa = T + (((size_t)b * STF + T_IDX[tt]) * PP + p) * DD;
            ya = S + (((size_t)b * SSF + S_IDX[tt]) * PP + p) * DD;
        }
        xb = sh; yb = sh;
    }
    bool same = (xb == yb);

    float zx = 0.f, zy = 0.f, s = 0.f;
    #pragma unroll
    for (int i = 0; i < 8; i++){
        int off = i * 128 + lane * 4;
        float4 a  = *(const float4*)(xa + off);
        float4 b4 = *(const float4*)(xb + off);
        float4 c  = *(const float4*)(ya + off);
        float4 d  = same ? b4 : *(const float4*)(yb + off);
        float x0 = a.x - b4.x, x1 = a.y - b4.y, x2 = a.z - b4.z, x3 = a.w - b4.w;
        float y0 = c.x - d.x,  y1 = c.y - d.y,  y2 = c.z - d.z,  y3 = c.w - d.w;
        float e0 = __expf(x0), e1 = __expf(x1), e2 = __expf(x2), e3 = __expf(x3);
        zx += e0 + e1 + e2 + e3;
        s  += e0 * (x0 - y0) + e1 * (x1 - y1) + e2 * (x2 - y2) + e3 * (x3 - y3);
        zy += __expf(y0) + __expf(y1) + __expf(y2) + __expf(y3);
    }
    zx = warpSum(zx); zy = warpSum(zy); s = warpSum(s);

    if (lane == 0){
        float kl = s / zx - __logf(zx) + __logf(zy);
        res[w] = huber(kl);
    }
    __syncthreads();
    if (threadIdx.x == 0){
        double a1 = (double)res[0] + res[1] + res[2];
        double a2 = 3.0 * ((double)res[3] + res[4] + res[5] + res[6]);
        double a3 = 0.0;
        #pragma unroll
        for (int k = 7; k < 19; k++) a3 += (double)res[k];
        atomicAdd(&g_acc[0], a1);
        atomicAdd(&g_acc[1], a2);
        atomicAdd(&g_acc[2], a3);
        __threadfence();
        unsigned t = atomicAdd(&g_done, 1u);
        if (t == NKL - 1){
            out[0] = (float)(g_acc[0] / 3072.0 + g_acc[1] / 12288.0 + g_acc[2] / 12288.0);
        }
    }
}

// ---------------------------------------------------------------- launch

extern "C" void kernel_launch(void* const* d_in, const int* in_sizes, int n_in,
                              void* d_out, int out_size){
    const float* T  = (const float*)d_in[0];   // teacher (4,8,1024,1024)
    const float* S  = (const float*)d_in[1];   // student (4,4,1024,1024)
    const int*   rp = (const int*)d_in[2];     // ref_perm (256)
    const int*   sp = (const int*)d_in[3];     // shared_perm (256)
    float* out = (float*)d_out;

    k_gather_ref<<<dim3(NREF, BB), 256>>>(T, rp);
    k_gemm<<<dim3(MT, 2, BB), 256>>>(T);
    k_topk2<<<dim3(NREF / 8, BB), 256>>>();
    k_kl<<<dim3(NREF, BB), 608>>>(T, S, sp, rp, out);
}

// round 17
// speedup vs baseline: 1.0433x; 1.0433x over previous
#include <cuda_runtime.h>
#include <cuda_bf16.h>
#include <math.h>
#include <float.h>

// Problem constants
#define BB    4
#define STF   8      // teacher frames
#define SSF   4      // student frames
#define PP    1024
#define DD    1024
#define NREF  256
#define NTOP  4
#define ME    4096   // extra rows per batch (4 frames * 1024)
#define MT    32     // m-tiles (ME/128)
#define NKL   (NREF * BB)   // k_kl blocks = 1024

// Scratch (device globals; no allocation allowed)
__device__ __nv_bfloat16  g_rthb[BB][NREF][DD];  // normalized teacher ref rows (bf16)
__device__ float          g_pv  [BB][NREF][MT][4]; // per-mtile top4 values
__device__ int            g_pi  [BB][NREF][MT][4]; // per-mtile top4 indices
__device__ int            g_top [BB][NREF][NTOP];
__device__ double         g_acc [3];
__device__ unsigned       g_done;

// ---------------------------------------------------------------- helpers

__device__ __forceinline__ float warpSum(float v){
    #pragma unroll
    for (int o = 16; o > 0; o >>= 1) v += __shfl_xor_sync(0xffffffffu, v, o);
    return v;
}

__device__ __forceinline__ float blockSum256(float v, volatile float* sm){
    __syncthreads();
    int lane = threadIdx.x & 31, w = threadIdx.x >> 5;
    v = warpSum(v);
    if (lane == 0) sm[w] = v;
    __syncthreads();
    if (threadIdx.x == 0){
        float r = sm[0];
        #pragma unroll
        for (int i = 1; i < 8; i++) r += sm[i];
        sm[0] = r;
    }
    __syncthreads();
    return sm[0];
}

// insert candidate (v,i) into top-4 sorted desc (ties -> lower index first)
__device__ __forceinline__ void ins4(float v, int i, float* tv, int* ti){
    if (v > tv[3] || (v == tv[3] && i < ti[3])){
        tv[3] = v; ti[3] = i;
        #pragma unroll
        for (int k = 3; k > 0; k--){
            bool sw = (tv[k] > tv[k-1]) || (tv[k] == tv[k-1] && ti[k] < ti[k-1]);
            if (sw){
                float fv = tv[k]; tv[k] = tv[k-1]; tv[k-1] = fv;
                int   fi = ti[k]; ti[k] = ti[k-1]; ti[k-1] = fi;
            } else break;
        }
    }
}

__device__ __forceinline__ float huber(float kl){
    float ax = fabsf(kl);
    return (ax < 0.5f) ? (ax * ax) : (ax - 0.25f);
}

// ---------------------------------------------------------------- mma helpers

__device__ __forceinline__ void ldsm4(unsigned& r0, unsigned& r1, unsigned& r2, unsigned& r3,
                                      unsigned addr){
    asm volatile("ldmatrix.sync.aligned.m8n8.x4.shared.b16 {%0,%1,%2,%3}, [%4];"
                 : "=r"(r0), "=r"(r1), "=r"(r2), "=r"(r3) : "r"(addr));
}
__device__ __forceinline__ void mma16816(float* c, const unsigned* a, const unsigned* b){
    asm volatile("mma.sync.aligned.m16n8k16.row.col.f32.bf16.bf16.f32 "
                 "{%0,%1,%2,%3}, {%4,%5,%6,%7}, {%8,%9}, {%0,%1,%2,%3};"
                 : "+f"(c[0]), "+f"(c[1]), "+f"(c[2]), "+f"(c[3])
                 : "r"(a[0]), "r"(a[1]), "r"(a[2]), "r"(a[3]), "r"(b[0]), "r"(b[1]));
}
__device__ __forceinline__ unsigned f2bf2(float lo, float hi){
    __nv_bfloat162 h = __floats2bfloat162_rn(lo, hi);
    return *(unsigned*)&h;
}

// ---------------------------------------------------------------- kernels

// Normalize teacher ref rows (frame 0) to bf16. grid(NREF, BB), 256 thr.
// Also zeroes the loss accumulators / ticket (block 0,0).
__global__ void k_gather_ref(const float* __restrict__ T, const int* __restrict__ rp){
    __shared__ float sm[8];
    int n = blockIdx.x, b = blockIdx.y, tid = threadIdx.x;
    if (n == 0 && b == 0 && tid == 0){
        g_acc[0] = 0.0; g_acc[1] = 0.0; g_acc[2] = 0.0;
        g_done = 0u;
    }
    int p = rp[n];
    const float* tr = T + (((size_t)b * STF + 0) * PP + p) * DD;
    float xv[4], ss = 0.f;
    #pragma unroll
    for (int j = 0; j < 4; j++){
        int idx = tid + j * 256;
        xv[j] = tr[idx];
        ss += xv[j] * xv[j];
    }
    ss = blockSum256(ss, sm);
    float inv = 1.f / fmaxf(sqrtf(ss), 1e-12f);
    #pragma unroll
    for (int j = 0; j < 4; j++){
        int idx = tid + j * 256;
        g_rthb[b][n][idx] = __float2bfloat16(xv[j] * inv);
    }
}

// bf16 tensor-core GEMM + fused extra-row norms + fused per-block top-4.
// Block tile 128(ref) x 128(extra) x 32(k). 8 warps: 2(ref) x 4(extra).
// Single smem buffer; next tile prefetched into registers during the mma phase.
#define LDSS 40   // smem row stride in bf16 elems
__global__ void __launch_bounds__(256, 2) k_gemm(const float* __restrict__ T){
    __shared__ __align__(16) unsigned char sbuf[20480]; // As|Bs, reused for candidates
    __shared__ float sm_inv[128];
    __nv_bfloat16 (*As)[LDSS] = reinterpret_cast<__nv_bfloat16(*)[LDSS]>(sbuf);
    __nv_bfloat16 (*Bs)[LDSS] = reinterpret_cast<__nv_bfloat16(*)[LDSS]>(sbuf + 10240);
    float (*cv)[4][4] = reinterpret_cast<float(*)[4][4]>(sbuf);        // 8 KB
    int   (*ci)[4][4] = reinterpret_cast<int  (*)[4][4]>(sbuf + 8192); // 8 KB

    int mt = blockIdx.x, nt = blockIdx.y, b = blockIdx.z;
    int tid = threadIdx.x, lane = tid & 31, warp = tid >> 5;
    int wn = warp & 1;    // ref-dim warp (64 rows)
    int wm = warp >> 1;   // extra-dim warp (32 rows)

    const __nv_bfloat16* A = &g_rthb[b][nt * 128][0];
    int m0 = mt * 128;
    int frame = 2 * (m0 >> 10) + 1;
    const float* Bp = T + (((size_t)b * STF + frame) * PP + (m0 & 1023)) * DD;

    float acc[4][4][4];
    #pragma unroll
    for (int i = 0; i < 4; i++)
        #pragma unroll
        for (int j = 0; j < 4; j++)
            #pragma unroll
            for (int q = 0; q < 4; q++) acc[i][j][q] = 0.f;

    unsigned sA = (unsigned)__cvta_generic_to_shared(&As[0][0]);
    unsigned sB = (unsigned)__cvta_generic_to_shared(&Bs[0][0]);

    int row_a = tid >> 1;
    int csel  = (tid & 1) * 16;
    float ssq = 0.f;   // partial sum of squares of this thread's B halves

    uint4  ar0, ar1;
    float4 br0, br1, br2, br3;
    {
        const uint4*  ap = (const uint4*)(A + (size_t)row_a * DD + csel);
        const float4* bp = (const float4*)(Bp + (size_t)row_a * DD + csel);
        ar0 = ap[0]; ar1 = ap[1];
        br0 = bp[0]; br1 = bp[1]; br2 = bp[2]; br3 = bp[3];
    }

    for (int kt = 0; kt < DD / 32; kt++){
        *(uint4*)&As[row_a][csel]     = ar0;
        *(uint4*)&As[row_a][csel + 8] = ar1;
        ssq += br0.x*br0.x + br0.y*br0.y + br0.z*br0.z + br0.w*br0.w
             + br1.x*br1.x + br1.y*br1.y + br1.z*br1.z + br1.w*br1.w
             + br2.x*br2.x + br2.y*br2.y + br2.z*br2.z + br2.w*br2.w
             + br3.x*br3.x + br3.y*br3.y + br3.z*br3.z + br3.w*br3.w;
        uint4 bb0, bb1;
        bb0.x = f2bf2(br0.x, br0.y); bb0.y = f2bf2(br0.z, br0.w);
        bb0.z = f2bf2(br1.x, br1.y); bb0.w = f2bf2(br1.z, br1.w);
        bb1.x = f2bf2(br2.x, br2.y); bb1.y = f2bf2(br2.z, br2.w);
        bb1.z = f2bf2(br3.x, br3.y); bb1.w = f2bf2(br3.z, br3.w);
        *(uint4*)&Bs[row_a][csel]     = bb0;
        *(uint4*)&Bs[row_a][csel + 8] = bb1;
        __syncthreads();

        if (kt < DD / 32 - 1){
            int k0 = (kt + 1) * 32;
            const uint4*  ap = (const uint4*)(A + (size_t)row_a * DD + k0 + csel);
            const float4* bp = (const float4*)(Bp + (size_t)row_a * DD + k0 + csel);
            ar0 = ap[0]; ar1 = ap[1];
            br0 = bp[0]; br1 = bp[1]; br2 = bp[2]; br3 = bp[3];
        }

        #pragma unroll
        for (int kk = 0; kk < 32; kk += 16){
            unsigned af[4][4];
            #pragma unroll
            for (int mi = 0; mi < 4; mi++){
                int r = wn * 64 + mi * 16 + (lane & 15);
                int c = kk + ((lane >> 4) << 3);
                ldsm4(af[mi][0], af[mi][1], af[mi][2], af[mi][3],
                      sA + (unsigned)((r * LDSS + c) * 2));
            }
            unsigned bf[4][2];
            #pragma unroll
            for (int pr = 0; pr < 2; pr++){
                int r = wm * 32 + pr * 16 + (lane & 7) + ((lane >> 4) << 3);
                int c = kk + (((lane >> 3) & 1) << 3);
                unsigned t0, t1, t2, t3;
                ldsm4(t0, t1, t2, t3, sB + (unsigned)((r * LDSS + c) * 2));
                bf[pr*2  ][0] = t0; bf[pr*2  ][1] = t1;
                bf[pr*2+1][0] = t2; bf[pr*2+1][1] = t3;
            }
            #pragma unroll
            for (int mi = 0; mi < 4; mi++)
                #pragma unroll
                for (int ni = 0; ni < 4; ni++)
                    mma16816(acc[mi][ni], af[mi], bf[ni]);
        }
        __syncthreads();
    }

    // ---- fused inverse norms (per local extra row) ----
    ssq += __shfl_xor_sync(0xffffffffu, ssq, 1);
    if ((tid & 1) == 0)
        sm_inv[row_a] = 1.f / fmaxf(sqrtf(ssq), 1e-12f);
    __syncthreads();

    // ---- fused per-block top-4 per ref row ----
    int gm = lane >> 2, gn = (lane & 3) * 2;
    #pragma unroll
    for (int mi = 0; mi < 4; mi++){
        #pragma unroll
        for (int h = 0; h < 2; h++){
            int r = wn * 64 + mi * 16 + gm + h * 8;   // local ref row
            float tv[4] = {-FLT_MAX, -FLT_MAX, -FLT_MAX, -FLT_MAX};
            int   ti[4] = {0x7fffffff, 0x7fffffff, 0x7fffffff, 0x7fffffff};
            #pragma unroll
            for (int ni = 0; ni < 4; ni++){
                int c = wm * 32 + ni * 8 + gn;
                ins4(acc[mi][ni][h*2+0] * sm_inv[c],     m0 + c,     tv, ti);
                ins4(acc[mi][ni][h*2+1] * sm_inv[c + 1], m0 + c + 1, tv, ti);
            }
            #pragma unroll
            for (int st = 1; st <= 2; st <<= 1){
                float ov[4]; int oi[4];
                #pragma unroll
                for (int k = 0; k < 4; k++){
                    ov[k] = __shfl_xor_sync(0xffffffffu, tv[k], st);
                    oi[k] = __shfl_xor_sync(0xffffffffu, ti[k], st);
                }
                #pragma unroll
                for (int k = 0; k < 4; k++) ins4(ov[k], oi[k], tv, ti);
            }
            if ((lane & 3) == 0){
                #pragma unroll
                for (int k = 0; k < 4; k++){ cv[r][wm][k] = tv[k]; ci[r][wm][k] = ti[k]; }
            }
        }
    }
    __syncthreads();

    if (tid < 128){
        float tv[4] = {-FLT_MAX, -FLT_MAX, -FLT_MAX, -FLT_MAX};
        int   ti[4] = {0x7fffffff, 0x7fffffff, 0x7fffffff, 0x7fffffff};
        #pragma unroll
        for (int w = 0; w < 4; w++)
            #pragma unroll
            for (int k = 0; k < 4; k++) ins4(cv[tid][w][k], ci[tid][w][k], tv, ti);
        int n = nt * 128 + tid;
        *(float4*)&g_pv[b][n][mt][0] = make_float4(tv[0], tv[1], tv[2], tv[3]);
        *(int4*)  &g_pi[b][n][mt][0] = make_int4(ti[0], ti[1], ti[2], ti[3]);
    }
}

// Warp-parallel final top-4 reduce over 32 m-tile candidate sets.
// 8 warps/block, warp w handles (b, n = blockIdx.x*8 + w). grid(NREF/8, BB).
__global__ void k_topk2(){
    int w = threadIdx.x >> 5, lane = threadIdx.x & 31;
    int n = blockIdx.x * 8 + w, b = blockIdx.y;
    float4 pv = *(const float4*)&g_pv[b][n][lane][0];
    int4   pi = *(const int4*)  &g_pi[b][n][lane][0];
    float tv[4] = {-FLT_MAX, -FLT_MAX, -FLT_MAX, -FLT_MAX};
    int   ti[4] = {0x7fffffff, 0x7fffffff, 0x7fffffff, 0x7fffffff};
    ins4(pv.x, pi.x, tv, ti); ins4(pv.y, pi.y, tv, ti);
    ins4(pv.z, pi.z, tv, ti); ins4(pv.w, pi.w, tv, ti);
    #pragma unroll
    for (int st = 1; st <= 16; st <<= 1){
        float ov[4]; int oi[4];
        #pragma unroll
        for (int k = 0; k < 4; k++){
            ov[k] = __shfl_xor_sync(0xffffffffu, tv[k], st);
            oi[k] = __shfl_xor_sync(0xffffffffu, ti[k], st);
        }
        #pragma unroll
        for (int k = 0; k < 4; k++) ins4(ov[k], oi[k], tv, ti);
    }
    if (lane == 0){
        #pragma unroll
        for (int k = 0; k < 4; k++) g_top[b][n][k] = ti[k];
    }
}

// All 19 KL tasks for one (b,n): one task per warp, 19 warps (608 threads).
// grid(NREF, BB). Ref rows read directly from T/S at rp[n].
//   w 0-2 : d1 (tt = w)
//   w 3-6 : d2 (j = w-3), t-invariant -> weighted x3
//   w 7-18: d3 (tt = (w-7)/4, j = (w-7)%4)
// Single streaming pass, no max-shift. Last block writes the final loss.
// launch_bounds(608, 3): cap regs at 35 so 3 blocks (57 warps) co-reside per SM.
__global__ void __launch_bounds__(608, 3) k_kl(const float* __restrict__ T,
                                               const float* __restrict__ S,
                                               const int* __restrict__ sp,
                                               const int* __restrict__ rp,
                                               float* __restrict__ out){
    __shared__ float res[19];
    int n = blockIdx.x, b = blockIdx.y;
    int w = threadIdx.x >> 5, lane = threadIdx.x & 31;

    const int T_IDX[3] = {2, 4, 6};
    const int S_IDX[3] = {1, 2, 3};
    int p  = sp[n];
    int pr = rp[n];
    const float* rt = T + (((size_t)b * STF + 0) * PP + pr) * DD;
    const float* rs = S + (((size_t)b * SSF + 0) * PP + pr) * DD;

    const float *xa, *xb, *ya, *yb;
    if (w < 3){
        int tt = w;
        xa = rt;
        xb = T + (((size_t)b * STF + T_IDX[tt]) * PP + p) * DD;
        ya = rs;
        yb = S + (((size_t)b * SSF + S_IDX[tt]) * PP + p) * DD;
    } else {
        int j = (w < 7) ? (w - 3) : ((w - 7) & 3);
        int m = g_top[b][n][j];
        int frame = 2 * (m >> 10) + 1;
        const float* sh = T + (((size_t)b * STF + frame) * PP + (m & 1023)) * DD;
        if (w < 7){
            xa = rt; ya = rs;
        } else {
            int tt = (w - 7) >> 2;
            xa = T + (((size_t)b * STF + T_IDX[tt]) * PP + p) * DD;
            ya = S + (((size_t)b * SSF + S_IDX[tt]) * PP + p) * DD;
        }
        xb = sh; yb = sh;
    }
    bool same = (xb == yb);

    float zx = 0.f, zy = 0.f, s = 0.f;
    #pragma unroll
    for (int i = 0; i < 8; i++){
        int off = i * 128 + lane * 4;
        float4 a  = *(const float4*)(xa + off);
        float4 b4 = *(const float4*)(xb + off);
        float4 c  = *(const float4*)(ya + off);
        float4 d  = same ? b4 : *(const float4*)(yb + off);
        float x0 = a.x - b4.x, x1 = a.y - b4.y, x2 = a.z - b4.z, x3 = a.w - b4.w;
        float y0 = c.x - d.x,  y1 = c.y - d.y,  y2 = c.z - d.z,  y3 = c.w - d.w;
        float e0 = __expf(x0), e1 = __expf(x1), e2 = __expf(x2), e3 = __expf(x3);
        zx += e0 + e1 + e2 + e3;
        s  += e0 * (x0 - y0) + e1 * (x1 - y1) + e2 * (x2 - y2) + e3 * (x3 - y3);
        zy += __expf(y0) + __expf(y1) + __expf(y2) + __expf(y3);
    }
    zx = warpSum(zx); zy = warpSum(zy); s = warpSum(s);

    if (lane == 0){
        float kl = s / zx - __logf(zx) + __logf(zy);
        res[w] = huber(kl);
    }
    __syncthreads();
    if (threadIdx.x == 0){
        double a1 = (double)res[0] + res[1] + res[2];
        double a2 = 3.0 * ((double)res[3] + res[4] + res[5] + res[6]);
        double a3 = 0.0;
        #pragma unroll
        for (int k = 7; k < 19; k++) a3 += (double)res[k];
        atomicAdd(&g_acc[0], a1);
        atomicAdd(&g_acc[1], a2);
        atomicAdd(&g_acc[2], a3);
        __threadfence();
        unsigned t = atomicAdd(&g_done, 1u);
        if (t == NKL - 1){
            out[0] = (float)(g_acc[0] / 3072.0 + g_acc[1] / 12288.0 + g_acc[2] / 12288.0);
        }
    }
}

// ---------------------------------------------------------------- launch

extern "C" void kernel_launch(void* const* d_in, const int* in_sizes, int n_in,
                              void* d_out, int out_size){
    const float* T  = (const float*)d_in[0];   // teacher (4,8,1024,1024)
    const float* S  = (const float*)d_in[1];   // student (4,4,1024,1024)
    const int*   rp = (const int*)d_in[2];     // ref_perm (256)
    const int*   sp = (const int*)d_in[3];     // shared_perm (256)
    float* out = (float*)d_out;

    k_gather_ref<<<dim3(NREF, BB), 256>>>(T, rp);
    k_gemm<<<dim3(MT, 2, BB), 256>>>(T);
    k_topk2<<<dim3(NREF / 8, BB), 256>>>();
    k_kl<<<dim3(NREF, BB), 608>>>(T, S, sp, rp, out);
}